// round 2
// baseline (speedup 1.0000x reference)
#include <cuda_runtime.h>
#include <cuda_bf16.h>
#include <string.h>

// Problem constants
#define BB 4096
#define SS 200
#define DD 64
#define HH 36
#define NROWS (BB * SS)          // 819200
#define BN_EPS 1e-5f
#define DICE_EPS 1e-3f

// ---------------- device scratch (no cudaMalloc allowed) ----------------
__device__ float g_hbuf[NROWS * HH];      // 118 MB: pre-BN hidden activations
__device__ float g_WbcT[HH * DD];         // (B - C)^T   [h][d]
__device__ float g_WdT [HH * DD];         // D^T         [h][d]
__device__ float g_WacT[HH * DD];         // (A + C)^T   [h][d]
__device__ float g_partS[BB * HH];        // per-block partial sums (deterministic)
__device__ float g_partQ[BB * HH];        // per-block partial sum-of-squares
__device__ float g_scaleA[HH];            // istd * gamma
__device__ float g_shiftC[HH];            // beta - mu * istd * gamma

// packed f32x2 FMA (Blackwell double-rate fp32 path; ptxas won't auto-fuse)
__device__ __forceinline__ void ffma2(float2& d, float2 a, float2 b) {
    unsigned long long ua, ub, ud;
    memcpy(&ua, &a, 8); memcpy(&ub, &b, 8); memcpy(&ud, &d, 8);
    asm("fma.rn.f32x2 %0, %1, %2, %0;" : "+l"(ud) : "l"(ua), "l"(ub));
    memcpy(&d, &ud, 8);
}

// ---------------- kernel 0: precompute weight combos ----------------
__global__ void k_init(const float* __restrict__ W1) {
    int t = threadIdx.x;
    for (int i = t; i < HH * DD; i += 256) {
        int h = i >> 6, d = i & 63;
        // W1 is [256][36] row-major; blocks: A rows 0-63, B 64-127, C 128-191, D 192-255
        float wA = W1[(d      ) * HH + h];
        float wB = W1[(64  + d) * HH + h];
        float wC = W1[(128 + d) * HH + h];
        float wD = W1[(192 + d) * HH + h];
        g_WbcT[i] = wB - wC;
        g_WdT [i] = wD;
        g_WacT[i] = wA + wC;
    }
}

// ---------------- kernel 1: per-b GEMM (200x64x36), write h, per-block stats ----------------
__global__ __launch_bounds__(224, 2)
void k_pass1(const float* __restrict__ history,
             const float* __restrict__ candidate,
             const float* __restrict__ b1) {
    __shared__ __align__(16) float sWeff[HH * DD];   // Weff^T [h][d]
    __shared__ float sCterm[HH];
    __shared__ float sCand[DD];
    __shared__ float sSum[7 * HH];
    __shared__ float sSq [7 * HH];

    const int b = blockIdx.x;
    const int t = threadIdx.x;
    const int wid = t >> 5, lane = t & 31;

    if (t < DD) sCand[t] = candidate[b * DD + t];
    __syncthreads();

    // Weff^T[h][d] = (B-C)^T[h][d] + cand[d] * D^T[h][d]
    for (int i = t; i < HH * DD; i += 224) {
        int d = i & 63;
        sWeff[i] = g_WbcT[i] + sCand[d] * g_WdT[i];
    }
    // cterm[h] = b1[h] + sum_d cand[d] * (A+C)^T[h][d]
    if (t < HH) {
        float c = b1[t];
        #pragma unroll
        for (int d = 0; d < DD; ++d) c += sCand[d] * g_WacT[t * DD + d];
        sCterm[t] = c;
    }
    __syncthreads();

    const bool active = (t < SS);
    float2 hreg[DD / 2];
    if (active) {
        const float4* rp = reinterpret_cast<const float4*>(
            history + ((size_t)b * SS + t) * DD);
        #pragma unroll
        for (int i = 0; i < 16; ++i) {
            float4 v = rp[i];
            hreg[2 * i]     = make_float2(v.x, v.y);
            hreg[2 * i + 1] = make_float2(v.z, v.w);
        }
    } else {
        #pragma unroll
        for (int i = 0; i < DD / 2; ++i) hreg[i] = make_float2(0.f, 0.f);
    }

    float* hout = g_hbuf + ((size_t)b * SS + (active ? t : 0)) * HH;
    float hq0 = 0.f, hq1 = 0.f, hq2 = 0.f;

    #pragma unroll 4
    for (int h = 0; h < HH; ++h) {
        const float4* wp = reinterpret_cast<const float4*>(sWeff + h * DD);
        float2 a0 = make_float2(0.f, 0.f);
        float2 a1 = make_float2(0.f, 0.f);
        #pragma unroll
        for (int i = 0; i < 16; ++i) {
            float4 wv = wp[i];   // broadcast LDS.128, conflict-free
            ffma2(a0, hreg[2 * i],     make_float2(wv.x, wv.y));
            ffma2(a1, hreg[2 * i + 1], make_float2(wv.z, wv.w));
        }
        float val = a0.x + a0.y + a1.x + a1.y + sCterm[h];
        if (!active) val = 0.f;

        int r = h & 3;
        if (r == 0) hq0 = val;
        else if (r == 1) hq1 = val;
        else if (r == 2) hq2 = val;
        else if (active) {
            float4 o = make_float4(hq0, hq1, hq2, val);
            *reinterpret_cast<float4*>(hout + (h - 3)) = o;
        }

        // warp tree-reduce (sum, sumsq) for this feature
        float s = val, q = val * val;
        #pragma unroll
        for (int off = 16; off; off >>= 1) {
            s += __shfl_xor_sync(0xffffffffu, s, off);
            q += __shfl_xor_sync(0xffffffffu, q, off);
        }
        if (lane == 0) { sSum[wid * HH + h] = s; sSq[wid * HH + h] = q; }
    }
    __syncthreads();

    // deterministic: write per-block partials (no atomics)
    if (t < HH) {
        float S = 0.f, Q = 0.f;
        #pragma unroll
        for (int w = 0; w < 7; ++w) { S += sSum[w * HH + t]; Q += sSq[w * HH + t]; }
        g_partS[b * HH + t] = S;
        g_partQ[b * HH + t] = Q;
    }
}

// ---------------- kernel 2: reduce partials, finalize BN affine ----------------
// grid = HH blocks, 256 threads; block f reduces 4096 partials for feature f.
__global__ void k_finalize(const float* __restrict__ gamma,
                           const float* __restrict__ beta) {
    __shared__ float rS[256], rQ[256];
    const int f = blockIdx.x;
    const int t = threadIdx.x;
    float S = 0.f, Q = 0.f;
    for (int b = t; b < BB; b += 256) {
        S += g_partS[b * HH + f];
        Q += g_partQ[b * HH + f];
    }
    rS[t] = S; rQ[t] = Q;
    __syncthreads();
    for (int off = 128; off; off >>= 1) {
        if (t < off) { rS[t] += rS[t + off]; rQ[t] += rQ[t + off]; }
        __syncthreads();
    }
    if (t == 0) {
        const float n = (float)NROWS;
        float mu  = rS[0] / n;
        float var = rQ[0] / n - mu * mu;
        float is  = rsqrtf(var + BN_EPS);
        float a   = is * gamma[f];
        g_scaleA[f] = a;
        g_shiftC[f] = beta[f] - mu * a;
    }
}

// ---------------- kernel 3: BN+Dice+W2 -> weights -> weighted-sum pooling ----------------
__global__ __launch_bounds__(224, 2)
void k_pass2(const float* __restrict__ history,
             const float* __restrict__ alpha,
             const float* __restrict__ W2,
             const float* __restrict__ b2,
             float* __restrict__ out) {
    __shared__ float sA[HH], sC[HH], sW2[HH];
    __shared__ float sPool[7 * DD];
    __shared__ float sAlpha, sB2;

    const int b = blockIdx.x;
    const int t = threadIdx.x;
    const int wid = t >> 5, lane = t & 31;

    if (t < HH) { sA[t] = g_scaleA[t]; sC[t] = g_shiftC[t]; sW2[t] = W2[t]; }
    if (t == 0) { sAlpha = alpha[0]; sB2 = b2[0]; }
    __syncthreads();

    const bool active = (t < SS);
    float w = 0.f;
    if (active) {
        float y[HH];
        const float4* hp = reinterpret_cast<const float4*>(
            g_hbuf + ((size_t)b * SS + t) * HH);
        #pragma unroll
        for (int i = 0; i < 9; ++i) {
            float4 v = hp[i];
            y[4 * i + 0] = fmaf(v.x, sA[4 * i + 0], sC[4 * i + 0]);
            y[4 * i + 1] = fmaf(v.y, sA[4 * i + 1], sC[4 * i + 1]);
            y[4 * i + 2] = fmaf(v.z, sA[4 * i + 2], sC[4 * i + 2]);
            y[4 * i + 3] = fmaf(v.w, sA[4 * i + 3], sC[4 * i + 3]);
        }
        float sy = 0.f, sy2 = 0.f;
        #pragma unroll
        for (int j = 0; j < HH; ++j) { sy += y[j]; sy2 += y[j] * y[j]; }
        const float inv = 1.f / (float)HH;
        float avg = sy * inv;
        float var = sy2 * inv - avg * avg;
        float is  = rsqrtf(var + DICE_EPS);
        float al  = sAlpha;
        float acc = sB2;
        #pragma unroll
        for (int j = 0; j < HH; ++j) {
            float xs = (y[j] - avg) * is;
            float ps = 1.f / (1.f + __expf(-xs));
            float f  = ps + (1.f - ps) * al;
            acc += y[j] * f * sW2[j];
        }
        w = acc;
    }

    float acc[DD];
    if (active) {
        const float4* rp = reinterpret_cast<const float4*>(
            history + ((size_t)b * SS + t) * DD);
        #pragma unroll
        for (int i = 0; i < 16; ++i) {
            float4 v = rp[i];
            acc[4 * i + 0] = w * v.x;
            acc[4 * i + 1] = w * v.y;
            acc[4 * i + 2] = w * v.z;
            acc[4 * i + 3] = w * v.w;
        }
    } else {
        #pragma unroll
        for (int d = 0; d < DD; ++d) acc[d] = 0.f;
    }

    // butterfly reduce the 64-vector across the warp
    #pragma unroll
    for (int off = 16; off; off >>= 1) {
        #pragma unroll
        for (int d = 0; d < DD; ++d)
            acc[d] += __shfl_xor_sync(0xffffffffu, acc[d], off);
    }
    if (lane == 0) {
        #pragma unroll
        for (int d = 0; d < DD; ++d) sPool[wid * DD + d] = acc[d];
    }
    __syncthreads();

    if (t < DD) {
        float s = 0.f;
        #pragma unroll
        for (int k = 0; k < 7; ++k) s += sPool[k * DD + t];
        out[b * DD + t] = s;
    }
}

// ---------------- launch ----------------
extern "C" void kernel_launch(void* const* d_in, const int* in_sizes, int n_in,
                              void* d_out, int out_size) {
    const float* history   = (const float*)d_in[0];
    const float* candidate = (const float*)d_in[1];
    const float* W1        = (const float*)d_in[2];
    const float* b1        = (const float*)d_in[3];
    const float* gamma     = (const float*)d_in[4];
    const float* beta      = (const float*)d_in[5];
    const float* alpha     = (const float*)d_in[6];
    const float* W2        = (const float*)d_in[7];
    const float* b2        = (const float*)d_in[8];
    float* out = (float*)d_out;

    k_init<<<1, 256>>>(W1);
    k_pass1<<<BB, 224>>>(history, candidate, b1);
    k_finalize<<<HH, 256>>>(gamma, beta);
    k_pass2<<<BB, 224>>>(history, alpha, W2, b2, out);
}